// round 14
// baseline (speedup 1.0000x reference)
#include <cuda_runtime.h>
#include <cuda_fp16.h>
#include <cstdint>
#include <math.h>

// ---------------------------------------------------------------------------
// Problem constants
// ---------------------------------------------------------------------------
#define NROWS     8192     // rows in z_i (and z_j)
#define DIM       512      // feature dim
#define BROWS     16384    // combined B rows (zi ++ zj)

#define BM        128      // CTA tile M
#define BN        128      // CTA tile N
#define BK        64       // K chunk (fp16 elems) = 128 bytes/row
#define CHUNKS    (DIM / BK)   // 8
#define STAGES    3

#define CHUNK_A_BYTES (BM * BK * 2)          // 16384
#define CHUNK_B_BYTES (BN * BK * 2)          // 16384
#define STAGE_BYTES   (CHUNK_A_BYTES + CHUNK_B_BYTES)  // 32768
#define SMEM_TOTAL    (STAGES * STAGE_BYTES)           // 98304 -> 2 CTAs/SM

#define NEG_TILES 4096     // 64 x 64 full tiles for zi x zj
#define POS_TILES 2080     // upper triangle incl diag of 64x64 blocks (zi x zi)
#define TOTAL_TILES (NEG_TILES + POS_TILES)  // 6176

// ---------------------------------------------------------------------------
// Global scratch (allocation-free rules: __device__ globals)
// ---------------------------------------------------------------------------
__device__ __half g_z[(size_t)BROWS * DIM];   // 16 MB: rows 0..8191 zi, 8192.. zj
__device__ double g_pos;
__device__ double g_neg;
__device__ unsigned int g_done;

// ---------------------------------------------------------------------------
// PTX helpers — only sm_80-era features (PTX target is plain sm_103; no tcgen05)
// ---------------------------------------------------------------------------
__device__ __forceinline__ uint32_t smem_to_u32(const void* p) {
    uint32_t a;
    asm("{ .reg .u64 t; cvta.to.shared.u64 t, %1; cvt.u32.u64 %0, t; }" : "=r"(a) : "l"(p));
    return a;
}

#define SWZ(off) ((off) ^ (((off) >> 3) & 0x70u))   // SW128 swizzle for 128B rows

__device__ __forceinline__ void cp_async16(uint32_t dst_smem, const void* src) {
    asm volatile("cp.async.cg.shared.global [%0], [%1], 16;" :: "r"(dst_smem), "l"(src));
}
#define CP_ASYNC_COMMIT() asm volatile("cp.async.commit_group;" ::: "memory")
#define CP_ASYNC_WAIT_1() asm volatile("cp.async.wait_group 1;" ::: "memory")
#define CP_ASYNC_WAIT_0() asm volatile("cp.async.wait_group 0;" ::: "memory")

__device__ __forceinline__ void ldmatrix_x4(uint32_t* r, uint32_t addr) {
    asm volatile("ldmatrix.sync.aligned.m8n8.x4.shared.b16 {%0,%1,%2,%3}, [%4];"
                 : "=r"(r[0]), "=r"(r[1]), "=r"(r[2]), "=r"(r[3]) : "r"(addr));
}

// D = A * B^T accumulate: mma.sync m16n8k16, fp16 in, fp16 accum (2 packed regs)
__device__ __forceinline__ void mma_f16(uint32_t* c, const uint32_t* a, uint32_t b0, uint32_t b1) {
    asm volatile(
        "mma.sync.aligned.m16n8k16.row.col.f16.f16.f16.f16 "
        "{%0,%1}, {%2,%3,%4,%5}, {%6,%7}, {%0,%1};"
        : "+r"(c[0]), "+r"(c[1])
        : "r"(a[0]), "r"(a[1]), "r"(a[2]), "r"(a[3]), "r"(b0), "r"(b1));
}

// ---------------------------------------------------------------------------
// Kernel 1: L2-normalize rows into fp16 g_z. One warp per row, 4 independent
// float4 loads per lane (MLP=4). Also resets accumulators + completion counter.
// ---------------------------------------------------------------------------
__global__ __launch_bounds__(256) void norm_kernel(const float* __restrict__ zi,
                                                   const float* __restrict__ zj) {
    const int tid  = threadIdx.x;
    const int lane = tid & 31;
    const int row  = blockIdx.x * 8 + (tid >> 5);   // 2048 blocks x 8 warps
    if (blockIdx.x == 0 && tid == 0) { g_pos = 0.0; g_neg = 0.0; g_done = 0u; }

    const float* src = (row < NROWS) ? (zi + (size_t)row * DIM)
                                     : (zj + (size_t)(row - NROWS) * DIM);
    const float4* s4 = reinterpret_cast<const float4*>(src);
    float4 v[4];
    #pragma unroll
    for (int k = 0; k < 4; k++) v[k] = s4[lane + 32 * k];

    float ss = 0.0f;
    #pragma unroll
    for (int k = 0; k < 4; k++)
        ss += v[k].x * v[k].x + v[k].y * v[k].y + v[k].z * v[k].z + v[k].w * v[k].w;
    #pragma unroll
    for (int off = 16; off > 0; off >>= 1)
        ss += __shfl_xor_sync(0xFFFFFFFFu, ss, off);

    float scale = 1.0f / fmaxf(sqrtf(ss), 1e-12f);

    __half2* dst = reinterpret_cast<__half2*>(g_z + (size_t)row * DIM);
    #pragma unroll
    for (int k = 0; k < 4; k++) {
        int e = lane + 32 * k;
        dst[e * 2 + 0] = __floats2half2_rn(v[k].x * scale, v[k].y * scale);
        dst[e * 2 + 1] = __floats2half2_rn(v[k].z * scale, v[k].w * scale);
    }
}

// ---------------------------------------------------------------------------
// Kernel 2: fused GEMM (mma.sync fp16) + weighted exp-sum epilogue.
// 128x128 tiles, 4 warps (64x64 warp tile), 3-stage cp.async pipeline,
// 2 CTAs/SM, register double-buffered fragments, QUARTER-GRAIN interleave:
//   ldB01 -> 8 MMA -> ldB23 -> 8 MMA -> ldA01 -> 8 MMA -> ldA23 -> 8 MMA
// plus the next-next chunk's cp.asyncs spread 4-per-kstep.
// Tile decode (1-D grid, 6176 tiles):
//   idx < 4096 : neg tile: tm = idx&63, B rows = NROWS + (idx>>6)*128, w=1
//   idx >= 4096: pos tile p -> lower-tri (t,i), i<=t: tm=i, B rows = t*128,
//                w = (i==t) ? 1 : 2   (symmetry of zi x zi^T)
// Last CTA computes the final loss (fused finish).
// ---------------------------------------------------------------------------
__global__ __launch_bounds__(128, 2) void gemm_kernel(float* __restrict__ out) {
    extern __shared__ __align__(1024) char smem[];
    const uint32_t sb = smem_to_u32(smem);
    const int tid   = threadIdx.x;
    const int wid   = tid >> 5;
    const int lane  = tid & 31;
    const int warpM = (wid & 1) * 64;
    const int warpN = (wid >> 1) * 64;

    // ---- tile decode ----
    int tm, rowB;
    float wtile;
    bool is_pos;
    {
        int idx = blockIdx.x;
        if (idx < NEG_TILES) {
            tm    = idx & 63;
            rowB  = NROWS + (idx >> 6) * BN;
            wtile = 1.0f;
            is_pos = false;
        } else {
            int p = idx - NEG_TILES;                    // 0 .. 2079
            int t = (int)((sqrtf((float)(8 * p + 1)) - 1.0f) * 0.5f);
            while ((t + 1) * (t + 2) / 2 <= p) t++;
            while (t * (t + 1) / 2 > p) t--;
            int i = p - t * (t + 1) / 2;                // 0 .. t
            tm    = i;
            rowB  = t * BN;
            wtile = (i == t) ? 1.0f : 2.0f;
            is_pos = true;
        }
    }

    const char* gzA = reinterpret_cast<const char*>(g_z) + (size_t)tm * BM * (DIM * 2);
    const char* gzB = reinterpret_cast<const char*>(g_z) + (size_t)rowB * (DIM * 2);

    uint32_t acc[4][8][2];    // fp16x2 accumulators: 64 regs
    #pragma unroll
    for (int i = 0; i < 4; i++)
        #pragma unroll
        for (int j = 0; j < 8; j++) { acc[i][j][0] = 0u; acc[i][j][1] = 0u; }

    // -------- chunk loader (full, prologue only): 16 x cp.async(16B) --------
    auto load_chunk = [&](int c, int st) {
        uint32_t stA = sb + st * STAGE_BYTES;
        uint32_t stB = stA + CHUNK_A_BYTES;
        const char* srcA = gzA + c * (BK * 2);
        const char* srcB = gzB + c * (BK * 2);
        #pragma unroll
        for (int i = 0; i < 8; i++) {
            int u = tid + i * 128;
            int r = u >> 3, c16 = u & 7;
            uint32_t off = (uint32_t)(r * 128 + c16 * 16);
            cp_async16(stA + SWZ(off), srcA + (size_t)r * (DIM * 2) + c16 * 16);
        }
        #pragma unroll
        for (int i = 0; i < 8; i++) {
            int u = tid + i * 128;
            int r = u >> 3, c16 = u & 7;
            uint32_t off = (uint32_t)(r * 128 + c16 * 16);
            cp_async16(stB + SWZ(off), srcB + (size_t)r * (DIM * 2) + c16 * 16);
        }
        CP_ASYNC_COMMIT();
    };

    // partial loader: 4 of 16 cp.asyncs (part 0..3); A on parts 0-1, B on 2-3
    auto load_chunk_part = [&](int c, int st, int part) {
        uint32_t stA = sb + st * STAGE_BYTES;
        uint32_t stB = stA + CHUNK_A_BYTES;
        const char* srcA = gzA + c * (BK * 2);
        const char* srcB = gzB + c * (BK * 2);
        if (part < 2) {
            #pragma unroll
            for (int i = 0; i < 4; i++) {
                int u = tid + (part * 4 + i) * 128;
                int r = u >> 3, c16 = u & 7;
                uint32_t off = (uint32_t)(r * 128 + c16 * 16);
                cp_async16(stA + SWZ(off), srcA + (size_t)r * (DIM * 2) + c16 * 16);
            }
        } else {
            #pragma unroll
            for (int i = 0; i < 4; i++) {
                int u = tid + ((part - 2) * 4 + i) * 128;
                int r = u >> 3, c16 = u & 7;
                uint32_t off = (uint32_t)(r * 128 + c16 * 16);
                cp_async16(stB + SWZ(off), srcB + (size_t)r * (DIM * 2) + c16 * 16);
            }
        }
        if (part == 3) CP_ASYNC_COMMIT();
    };

    // -------- double-buffered fragment registers --------
    uint32_t af[2][4][4], bf[2][4][4];     // 64 regs

    const int ldRow  = lane & 15;
    const int ldColB = (lane >> 4) << 4;

    // quarter preloads: 2 ldmatrix.x4 each
    auto preload_A2 = [&](int st, int ks, int buf, int mb0) {
        uint32_t stA = sb + st * STAGE_BYTES;
        #pragma unroll
        for (int mb = mb0; mb < mb0 + 2; mb++) {
            uint32_t off = (uint32_t)((warpM + mb * 16 + ldRow) * 128 + ks * 32 + ldColB);
            ldmatrix_x4(af[buf][mb], stA + SWZ(off));
        }
    };
    auto preload_B2 = [&](int st, int ks, int buf, int nb0) {
        uint32_t stB = sb + st * STAGE_BYTES + CHUNK_A_BYTES;
        #pragma unroll
        for (int nb = nb0; nb < nb0 + 2; nb++) {
            uint32_t off = (uint32_t)((warpN + nb * 16 + ldRow) * 128 + ks * 32 + ldColB);
            ldmatrix_x4(bf[buf][nb], stB + SWZ(off));
        }
    };

    // 8 MMAs: mBlock mb x all 8 n-fragments of buffer buf
    auto mma_q = [&](int buf, int mb) {
        #pragma unroll
        for (int nb = 0; nb < 4; nb++) {
            mma_f16(acc[mb][nb * 2 + 0], af[buf][mb], bf[buf][nb][0], bf[buf][nb][2]);
            mma_f16(acc[mb][nb * 2 + 1], af[buf][mb], bf[buf][nb][1], bf[buf][nb][3]);
        }
    };

    // quarter-interleaved: 2-LDSM groups between 8-MMA groups
    auto kstep_interleaved = [&](int ldSt, int ldKs, int cur) {
        preload_B2(ldSt, ldKs, cur ^ 1, 0);
        mma_q(cur, 0);
        preload_B2(ldSt, ldKs, cur ^ 1, 2);
        mma_q(cur, 1);
        preload_A2(ldSt, ldKs, cur ^ 1, 0);
        mma_q(cur, 2);
        preload_A2(ldSt, ldKs, cur ^ 1, 2);
        mma_q(cur, 3);
    };

    // -------- prologue: fill stages, preload first fragments --------
    load_chunk(0, 0);
    load_chunk(1, 1);
    CP_ASYNC_WAIT_1();      // chunk 0 resident
    __syncthreads();
    preload_A2(0, 0, 0, 0);
    preload_A2(0, 0, 0, 2);
    preload_B2(0, 0, 0, 0);
    preload_B2(0, 0, 0, 2);

    int cur = 0;
    #pragma unroll 1
    for (int c = 0; c < CHUNKS; c++) {
        const int st = c % STAGES;
        const bool have_next2 = (c + 2 < CHUNKS);

        #pragma unroll
        for (int ks = 0; ks < 4; ks++) {
            if (have_next2) load_chunk_part(c + 2, (c + 2) % STAGES, ks);

            if (ks < 3) {
                kstep_interleaved(st, ks + 1, cur);
            } else if (c + 1 < CHUNKS) {
                // chunk boundary inside last kstep: wait next chunk, sync
                // (stage-reuse guard: all reads of stage st issued at ks=2's
                // preload, fenced by this barrier), then interleave next
                // chunk's kstep-0 LDSMs with this kstep's MMAs.
                if (have_next2) CP_ASYNC_WAIT_1();
                else            CP_ASYNC_WAIT_0();
                __syncthreads();
                kstep_interleaved((c + 1) % STAGES, 0, cur);
            } else {
                mma_q(cur, 0); mma_q(cur, 1); mma_q(cur, 2); mma_q(cur, 3);
            }
            cur ^= 1;
        }
    }

    // -------- epilogue: weighted sum of exp(10 * acc) --------
    float lsum = 0.0f;
    #pragma unroll
    for (int i = 0; i < 4; i++)
        #pragma unroll
        for (int j = 0; j < 8; j++)
            #pragma unroll
            for (int k = 0; k < 2; k++) {
                float2 f = __half22float2(*reinterpret_cast<const __half2*>(&acc[i][j][k]));
                lsum += __expf(10.0f * f.x) + __expf(10.0f * f.y);
            }
    lsum *= wtile;

    #pragma unroll
    for (int off = 16; off > 0; off >>= 1)
        lsum += __shfl_xor_sync(0xFFFFFFFFu, lsum, off);

    __shared__ double wsum[4];
    if (lane == 0) wsum[wid] = (double)lsum;
    __syncthreads();
    if (tid == 0) {
        double t = wsum[0] + wsum[1] + wsum[2] + wsum[3];
        atomicAdd(is_pos ? &g_pos : &g_neg, t);

        // fused finish: last CTA to complete computes the loss
        __threadfence();
        unsigned int prev = atomicAdd(&g_done, 1u);
        if (prev == TOTAL_TILES - 1) {
            double p = atomicAdd(&g_pos, 0.0);
            double n = atomicAdd(&g_neg, 0.0);
            out[0] = (float)(-log(p / (n + p)));
        }
    }
}

// ---------------------------------------------------------------------------
extern "C" void kernel_launch(void* const* d_in, const int* in_sizes, int n_in,
                              void* d_out, int out_size) {
    const float* zi = (const float*)d_in[0];
    const float* zj = (const float*)d_in[1];
    float* out = (float*)d_out;

    cudaFuncSetAttribute(gemm_kernel, cudaFuncAttributeMaxDynamicSharedMemorySize, SMEM_TOTAL);

    norm_kernel<<<BROWS / 8, 256>>>(zi, zj);
    gemm_kernel<<<TOTAL_TILES, 128, SMEM_TOTAL>>>(out);
}